// round 2
// baseline (speedup 1.0000x reference)
#include <cuda_runtime.h>

#define N_NODES 50000
#define N_EDGES 600000
#define DIM 128
#define LN_EPS 1e-5f

// ---------------- scratch (device globals; no allocation allowed) ----------------
__device__ __align__(16) float g_h[N_NODES * DIM];    // GEMM output of current layer
__device__ __align__(16) float g_tmp[N_NODES * DIM];  // layer-1 activation
__device__ float g_dinv[N_NODES];
__device__ int   g_cnt[N_NODES];
__device__ int   g_rowstart[N_NODES + 1];
__device__ int   g_cur[N_NODES];
__device__ int   g_csrsrc[N_EDGES];
__device__ float g_csrnorm[N_EDGES];

// ---------------- CSR build ----------------
__global__ void k_zero_cnt() {
    int i = blockIdx.x * blockDim.x + threadIdx.x;
    if (i < N_NODES) g_cnt[i] = 0;
}

__global__ void k_count(const int* __restrict__ ei) {
    int e = blockIdx.x * blockDim.x + threadIdx.x;
    if (e < N_EDGES) {
        int dst = ei[N_EDGES + e];
        atomicAdd(&g_cnt[dst], 1);
    }
}

// single-block scan over N_NODES + dinv compute + cursor init
__global__ void k_scan() {
    __shared__ int sh[1024];
    int tid = threadIdx.x;
    const int per = (N_NODES + 1023) / 1024;
    int base = tid * per;
    int s = 0;
    for (int i = 0; i < per; i++) {
        int idx = base + i;
        if (idx < N_NODES) s += g_cnt[idx];
    }
    sh[tid] = s;
    __syncthreads();
    for (int off = 1; off < 1024; off <<= 1) {
        int v = (tid >= off) ? sh[tid - off] : 0;
        __syncthreads();
        sh[tid] += v;
        __syncthreads();
    }
    int run = (tid == 0) ? 0 : sh[tid - 1];
    for (int i = 0; i < per; i++) {
        int idx = base + i;
        if (idx < N_NODES) {
            int c = g_cnt[idx];
            g_rowstart[idx] = run;
            g_cur[idx] = run;
            g_dinv[idx] = rsqrtf((float)c + 1.0f);
            run += c;
        }
    }
    if (tid == 1023) g_rowstart[N_NODES] = sh[1023];
}

__global__ void k_fill(const int* __restrict__ ei) {
    int e = blockIdx.x * blockDim.x + threadIdx.x;
    if (e < N_EDGES) {
        int src = ei[e];
        int dst = ei[N_EDGES + e];
        int p = atomicAdd(&g_cur[dst], 1);
        g_csrsrc[p] = src;
        g_csrnorm[p] = g_dinv[src] * g_dinv[dst];
    }
}

// ---------------- GEMM: H = X @ W  (X: [N,128], W: [128,128]) ----------------
// 64-row x 128-col tile per block, 256 threads, 4x8 register blocking.
__global__ void __launch_bounds__(256) k_gemm(const float* __restrict__ Xin,
                                              const float* __restrict__ W) {
    __shared__ float xs[64][32];
    __shared__ float ws[32][128];

    const float* X = Xin ? Xin : g_tmp;
    int tid = threadIdx.x;
    int tx = tid & 15;      // col group 0..15 -> cols tx*8 .. tx*8+7
    int ty = tid >> 4;      // row group 0..15 -> rows ty*4 .. ty*4+3
    int rowBase = blockIdx.x * 64;

    float acc[4][8];
#pragma unroll
    for (int r = 0; r < 4; r++)
#pragma unroll
        for (int c = 0; c < 8; c++) acc[r][c] = 0.0f;

    for (int kc = 0; kc < 128; kc += 32) {
        // load x tile: 64 rows x 32 k-values = 512 float4
#pragma unroll
        for (int i = tid; i < 512; i += 256) {
            int r = i >> 3, c = i & 7;
            int grow = rowBase + r;
            float4 v = make_float4(0.f, 0.f, 0.f, 0.f);
            if (grow < N_NODES)
                v = *(const float4*)&X[grow * 128 + kc + c * 4];
            *(float4*)&xs[r][c * 4] = v;
        }
        // load W tile: 32 k-rows x 128 cols = 1024 float4
#pragma unroll
        for (int i = tid; i < 1024; i += 256) {
            int r = i >> 5, c = i & 31;
            *(float4*)&ws[r][c * 4] = *(const float4*)&W[(kc + r) * 128 + c * 4];
        }
        __syncthreads();

#pragma unroll
        for (int kk = 0; kk < 32; kk++) {
            float4 w0 = *(float4*)&ws[kk][tx * 8];
            float4 w1 = *(float4*)&ws[kk][tx * 8 + 4];
#pragma unroll
            for (int r = 0; r < 4; r++) {
                float xv = xs[ty * 4 + r][kk];
                acc[r][0] += xv * w0.x; acc[r][1] += xv * w0.y;
                acc[r][2] += xv * w0.z; acc[r][3] += xv * w0.w;
                acc[r][4] += xv * w1.x; acc[r][5] += xv * w1.y;
                acc[r][6] += xv * w1.z; acc[r][7] += xv * w1.w;
            }
        }
        __syncthreads();
    }

#pragma unroll
    for (int r = 0; r < 4; r++) {
        int grow = rowBase + ty * 4 + r;
        if (grow < N_NODES) {
            *(float4*)&g_h[grow * 128 + tx * 8] =
                make_float4(acc[r][0], acc[r][1], acc[r][2], acc[r][3]);
            *(float4*)&g_h[grow * 128 + tx * 8 + 4] =
                make_float4(acc[r][4], acc[r][5], acc[r][6], acc[r][7]);
        }
    }
}

// ---------------- fused aggregation + bias + LayerNorm + ReLU (+ residual) ----------------
// one warp per node; full 128-wide row lives in 4 floats/lane.
__global__ void __launch_bounds__(256) k_agg_ln(const float* __restrict__ bias,
                                                const float* __restrict__ gam,
                                                const float* __restrict__ bet,
                                                const float* __restrict__ resid,
                                                float* __restrict__ outp) {
    int warp = (blockIdx.x * blockDim.x + threadIdx.x) >> 5;
    int lane = threadIdx.x & 31;
    if (warp >= N_NODES) return;
    int row = warp;

    float* out = outp ? outp : g_tmp;
    const float4* H4 = (const float4*)g_h;

    float di = g_dinv[row];
    float sl = di * di;
    float4 acc = H4[row * 32 + lane];
    acc.x *= sl; acc.y *= sl; acc.z *= sl; acc.w *= sl;

    int e0 = g_rowstart[row];
    int e1 = g_rowstart[row + 1];
    for (int e = e0; e < e1; e++) {
        int s = g_csrsrc[e];
        float nm = g_csrnorm[e];
        float4 v = H4[s * 32 + lane];
        acc.x += nm * v.x; acc.y += nm * v.y;
        acc.z += nm * v.z; acc.w += nm * v.w;
    }

    float4 bb = ((const float4*)bias)[lane];
    acc.x += bb.x; acc.y += bb.y; acc.z += bb.z; acc.w += bb.w;

    // mean
    float s4 = acc.x + acc.y + acc.z + acc.w;
#pragma unroll
    for (int o = 16; o; o >>= 1) s4 += __shfl_xor_sync(0xffffffffu, s4, o);
    float mu = s4 * (1.0f / 128.0f);

    float d0 = acc.x - mu, d1 = acc.y - mu, d2 = acc.z - mu, d3 = acc.w - mu;
    float q = d0 * d0 + d1 * d1 + d2 * d2 + d3 * d3;
#pragma unroll
    for (int o = 16; o; o >>= 1) q += __shfl_xor_sync(0xffffffffu, q, o);
    float inv = rsqrtf(q * (1.0f / 128.0f) + LN_EPS);

    float4 gg = ((const float4*)gam)[lane];
    float4 be = ((const float4*)bet)[lane];
    float4 o4;
    o4.x = fmaxf(d0 * inv * gg.x + be.x, 0.0f);
    o4.y = fmaxf(d1 * inv * gg.y + be.y, 0.0f);
    o4.z = fmaxf(d2 * inv * gg.z + be.z, 0.0f);
    o4.w = fmaxf(d3 * inv * gg.w + be.w, 0.0f);

    if (resid) {
        float4 rv = ((const float4*)resid)[row * 32 + lane];
        o4.x += rv.x; o4.y += rv.y; o4.z += rv.z; o4.w += rv.w;
    }
    ((float4*)out)[row * 32 + lane] = o4;
}

// ---------------- launch ----------------
extern "C" void kernel_launch(void* const* d_in, const int* in_sizes, int n_in,
                              void* d_out, int out_size) {
    const float* x   = (const float*)d_in[0];
    const int*   ei  = (const int*)d_in[1];   // int32 (JAX default x64-disabled)
    const float* W1  = (const float*)d_in[2];
    const float* b1  = (const float*)d_in[3];
    const float* g1  = (const float*)d_in[4];
    const float* lb1 = (const float*)d_in[5];
    const float* W2  = (const float*)d_in[6];
    const float* b2  = (const float*)d_in[7];
    const float* g2  = (const float*)d_in[8];
    const float* lb2 = (const float*)d_in[9];
    float* out = (float*)d_out;

    const int TB = 256;
    int gridN = (N_NODES + TB - 1) / TB;
    int gridE = (N_EDGES + TB - 1) / TB;
    int gridGemm = (N_NODES + 63) / 64;
    int gridAgg = (N_NODES * 32 + TB - 1) / TB;

    // CSR build (per replay; deterministic work)
    k_zero_cnt<<<gridN, TB>>>();
    k_count<<<gridE, TB>>>(ei);
    k_scan<<<1, 1024>>>();
    k_fill<<<gridE, TB>>>(ei);

    // layer 1: h = x@W1 ; tmp = relu(LN(agg(h) + b1))
    k_gemm<<<gridGemm, TB>>>(x, W1);
    k_agg_ln<<<gridAgg, TB>>>(b1, g1, lb1, nullptr, nullptr);

    // layer 2: h = tmp@W2 ; out = relu(LN(agg(h) + b2)) + x
    k_gemm<<<gridGemm, TB>>>(nullptr, W2);
    k_agg_ln<<<gridAgg, TB>>>(b2, g2, lb2, x, out);
}

// round 4
// speedup vs baseline: 2.3191x; 2.3191x over previous
#include <cuda_runtime.h>
#include <cuda_bf16.h>
#include <cstdint>

#define N_NODES 50000
#define N_EDGES 600000
#define LN_EPS 1e-5f
#define NT 391            // ceil(50000/128) M-tiles
#define GEMM_GRID 148
#define SCAN_BLOCKS 196   // ceil(50000/256)

// smem word layout for GEMM (uint32 units); A/B rows padded to 68 words (136 bf16)
#define ROWW 68
#define SA_HI 0
#define SA_LO 8704
#define SB_HI 17408
#define SB_LO 26112
#define GEMM_SMEM_WORDS 34816
#define GEMM_SMEM_BYTES (GEMM_SMEM_WORDS * 4)

// ---------------- device scratch ----------------
__device__ __align__(16) float g_h[N_NODES * 128];
__device__ __align__(16) float g_tmp[N_NODES * 128];
__device__ float g_dinv[N_NODES];
__device__ int   g_cnt[N_NODES];
__device__ int   g_rowstart[N_NODES + 1];
__device__ int   g_cur[N_NODES];
__device__ int   g_csrsrc[N_EDGES];
__device__ int   g_part[SCAN_BLOCKS];
__device__ int   g_partpre[SCAN_BLOCKS];
// bf16 W^T images (B layout: [n][k], linear): [layer][hi/lo]
__device__ __align__(16) uint4 g_wimg[2][2][2048];

// ---------------- CSR build ----------------
__global__ void k_zero_cnt() {
    int i = blockIdx.x * blockDim.x + threadIdx.x;
    if (i < N_NODES) g_cnt[i] = 0;
}

__global__ void k_count(const int* __restrict__ ei) {
    int e4 = blockIdx.x * blockDim.x + threadIdx.x;
    if (e4 < N_EDGES / 4) {
        int4 d = ((const int4*)(ei + N_EDGES))[e4];
        atomicAdd(&g_cnt[d.x], 1);
        atomicAdd(&g_cnt[d.y], 1);
        atomicAdd(&g_cnt[d.z], 1);
        atomicAdd(&g_cnt[d.w], 1);
    }
}

__global__ void k_scan1() {
    __shared__ int sh[256];
    int i = blockIdx.x * 256 + threadIdx.x;
    sh[threadIdx.x] = (i < N_NODES) ? g_cnt[i] : 0;
    __syncthreads();
#pragma unroll
    for (int o = 128; o; o >>= 1) {
        if (threadIdx.x < o) sh[threadIdx.x] += sh[threadIdx.x + o];
        __syncthreads();
    }
    if (threadIdx.x == 0) g_part[blockIdx.x] = sh[0];
}

__global__ void k_scan2() {
    __shared__ int sh[256];
    int t = threadIdx.x;
    int v = (t < SCAN_BLOCKS) ? g_part[t] : 0;
    sh[t] = v;
    __syncthreads();
#pragma unroll
    for (int o = 1; o < 256; o <<= 1) {
        int a = (t >= o) ? sh[t - o] : 0;
        __syncthreads();
        sh[t] += a;
        __syncthreads();
    }
    if (t < SCAN_BLOCKS) g_partpre[t] = sh[t] - v;
    if (t == SCAN_BLOCKS - 1) g_rowstart[N_NODES] = sh[t];
}

__global__ void k_scan3() {
    __shared__ int sh[256];
    int t = threadIdx.x;
    int i = blockIdx.x * 256 + t;
    int c = (i < N_NODES) ? g_cnt[i] : 0;
    sh[t] = c;
    __syncthreads();
#pragma unroll
    for (int o = 1; o < 256; o <<= 1) {
        int a = (t >= o) ? sh[t - o] : 0;
        __syncthreads();
        sh[t] += a;
        __syncthreads();
    }
    if (i < N_NODES) {
        int excl = sh[t] - c + g_partpre[blockIdx.x];
        g_rowstart[i] = excl;
        g_cur[i] = excl;
        g_dinv[i] = rsqrtf((float)c + 1.0f);
    }
}

__global__ void k_fill(const int* __restrict__ ei) {
    int e4 = blockIdx.x * blockDim.x + threadIdx.x;
    if (e4 < N_EDGES / 4) {
        int4 s = ((const int4*)ei)[e4];
        int4 d = ((const int4*)(ei + N_EDGES))[e4];
        g_csrsrc[atomicAdd(&g_cur[d.x], 1)] = s.x;
        g_csrsrc[atomicAdd(&g_cur[d.y], 1)] = s.y;
        g_csrsrc[atomicAdd(&g_cur[d.z], 1)] = s.z;
        g_csrsrc[atomicAdd(&g_cur[d.w], 1)] = s.w;
    }
}

// ---------------- W -> transposed bf16 hi/lo images (linear [n][k]) ----------------
__global__ void k_convW(const float* __restrict__ W, int layer) {
    __nv_bfloat16* hi = (__nv_bfloat16*)g_wimg[layer][0];
    __nv_bfloat16* lo = (__nv_bfloat16*)g_wimg[layer][1];
    for (int i = blockIdx.x * blockDim.x + threadIdx.x; i < 16384; i += blockDim.x * gridDim.x) {
        int n = i >> 7, k = i & 127;          // B[n][k] = W[k][n]
        float w = W[k * 128 + n];
        __nv_bfloat16 h = __float2bfloat16(w);
        __nv_bfloat16 l = __float2bfloat16(w - __bfloat162float(h));
        hi[n * 128 + k] = h;
        lo[n * 128 + k] = l;
    }
}

// ---------------- mma.sync bf16 split-precision GEMM ----------------
__device__ __forceinline__ uint32_t pack2(__nv_bfloat16 a, __nv_bfloat16 b) {
    return (uint32_t)__bfloat16_as_ushort(a) | ((uint32_t)__bfloat16_as_ushort(b) << 16);
}

__device__ __forceinline__ void mma_bf16(float* c, const uint32_t* a, const uint32_t* b) {
    asm volatile(
        "mma.sync.aligned.m16n8k16.row.col.f32.bf16.bf16.f32 "
        "{%0,%1,%2,%3}, {%4,%5,%6,%7}, {%8,%9}, {%0,%1,%2,%3};"
        : "+f"(c[0]), "+f"(c[1]), "+f"(c[2]), "+f"(c[3])
        : "r"(a[0]), "r"(a[1]), "r"(a[2]), "r"(a[3]), "r"(b[0]), "r"(b[1]));
}

// H = X @ W via D = Ah*Bh + Ah*Bl + Al*Bh, persistent CTAs over M-tiles of 128.
__global__ void __launch_bounds__(256, 1) k_gemm_mma(const float* __restrict__ Xin, int layer) {
    extern __shared__ uint32_t sw[];
    uint32_t* sAh = sw + SA_HI;
    uint32_t* sAl = sw + SA_LO;
    uint32_t* sBh = sw + SB_HI;
    uint32_t* sBl = sw + SB_LO;

    const float4* X4 = (const float4*)((layer == 0) ? Xin : g_tmp);
    int tid = threadIdx.x, wid = tid >> 5, lane = tid & 31;
    int g = lane >> 2, t = lane & 3;
    int wm = wid & 3, wn = wid >> 2;

    // stage B (W^T) hi/lo into padded smem, once
    {
        const uint4* Bh = g_wimg[layer][0];
        const uint4* Bl = g_wimg[layer][1];
#pragma unroll 4
        for (int i = tid; i < 2048; i += 256) {
            int n = i >> 4, kc = i & 15;
            *(uint4*)(sBh + n * ROWW + kc * 4) = Bh[i];
            *(uint4*)(sBl + n * ROWW + kc * 4) = Bl[i];
        }
    }
    __syncthreads();

    for (int tile = blockIdx.x; tile < NT; tile += gridDim.x) {
        int rowBase = tile * 128;

        // convert A tile fp32 -> bf16 hi/lo into padded smem
#pragma unroll 4
        for (int i = tid; i < 4096; i += 256) {      // 128 rows x 32 float4
            int r = i >> 5, c = i & 31;
            int grow = rowBase + r;
            float4 v = (grow < N_NODES) ? X4[grow * 32 + c] : make_float4(0.f, 0.f, 0.f, 0.f);
            __nv_bfloat16 h0 = __float2bfloat16(v.x), h1 = __float2bfloat16(v.y);
            __nv_bfloat16 h2 = __float2bfloat16(v.z), h3 = __float2bfloat16(v.w);
            __nv_bfloat16 l0 = __float2bfloat16(v.x - __bfloat162float(h0));
            __nv_bfloat16 l1 = __float2bfloat16(v.y - __bfloat162float(h1));
            __nv_bfloat16 l2 = __float2bfloat16(v.z - __bfloat162float(h2));
            __nv_bfloat16 l3 = __float2bfloat16(v.w - __bfloat162float(h3));
            *(uint2*)(sAh + r * ROWW + c * 2) = make_uint2(pack2(h0, h1), pack2(h2, h3));
            *(uint2*)(sAl + r * ROWW + c * 2) = make_uint2(pack2(l0, l1), pack2(l2, l3));
        }
        __syncthreads();

        float acc[2][8][4];
#pragma unroll
        for (int mi = 0; mi < 2; mi++)
#pragma unroll
            for (int ni = 0; ni < 8; ni++)
#pragma unroll
                for (int j = 0; j < 4; j++) acc[mi][ni][j] = 0.0f;

#pragma unroll
        for (int ks = 0; ks < 8; ks++) {
            int kw = ks * 8;
            uint32_t ah[2][4], al[2][4];
#pragma unroll
            for (int mi = 0; mi < 2; mi++) {
                int r0 = (wm * 32 + mi * 16 + g) * ROWW + kw + t;
                int r1 = r0 + 8 * ROWW;
                ah[mi][0] = sAh[r0]; ah[mi][1] = sAh[r1];
                ah[mi][2] = sAh[r0 + 4]; ah[mi][3] = sAh[r1 + 4];
                al[mi][0] = sAl[r0]; al[mi][1] = sAl[r1];
                al[mi][2] = sAl[r0 + 4]; al[mi][3] = sAl[r1 + 4];
            }
            uint32_t bh[8][2], bl[8][2];
#pragma unroll
            for (int ni = 0; ni < 8; ni++) {
                int nb = (wn * 64 + ni * 8 + g) * ROWW + kw + t;
                bh[ni][0] = sBh[nb]; bh[ni][1] = sBh[nb + 4];
                bl[ni][0] = sBl[nb]; bl[ni][1] = sBl[nb + 4];
            }
#pragma unroll
            for (int mi = 0; mi < 2; mi++)
#pragma unroll
                for (int ni = 0; ni < 8; ni++) {
                    mma_bf16(acc[mi][ni], ah[mi], bh[ni]);
                    mma_bf16(acc[mi][ni], ah[mi], bl[ni]);
                    mma_bf16(acc[mi][ni], al[mi], bh[ni]);
                }
        }

        // epilogue: fragments -> g_h fp32
#pragma unroll
        for (int mi = 0; mi < 2; mi++) {
            int r0 = rowBase + wm * 32 + mi * 16 + g;
            int r1 = r0 + 8;
#pragma unroll
            for (int ni = 0; ni < 8; ni++) {
                int col = wn * 64 + ni * 8 + t * 2;
                if (r0 < N_NODES)
                    *(float2*)&g_h[r0 * 128 + col] = make_float2(acc[mi][ni][0], acc[mi][ni][1]);
                if (r1 < N_NODES)
                    *(float2*)&g_h[r1 * 128 + col] = make_float2(acc[mi][ni][2], acc[mi][ni][3]);
            }
        }
        __syncthreads();
    }
}

// ---------------- fused aggregation + bias + LayerNorm + ReLU (+ residual) ----------------
__global__ void __launch_bounds__(256) k_agg_ln(const float* __restrict__ bias,
                                                const float* __restrict__ gam,
                                                const float* __restrict__ bet,
                                                const float* __restrict__ resid,
                                                float* __restrict__ outp) {
    int warp = (blockIdx.x * blockDim.x + threadIdx.x) >> 5;
    int lane = threadIdx.x & 31;
    if (warp >= N_NODES) return;
    int row = warp;

    float* out = outp ? outp : g_tmp;
    const float4* H4 = (const float4*)g_h;

    float di = g_dinv[row];
    float sl = di * di;
    float4 acc = H4[row * 32 + lane];
    acc.x *= sl; acc.y *= sl; acc.z *= sl; acc.w *= sl;

    int e = g_rowstart[row];
    int e1 = g_rowstart[row + 1];
    for (; e + 2 <= e1; e += 2) {
        int s0 = g_csrsrc[e], s1 = g_csrsrc[e + 1];
        float n0 = g_dinv[s0] * di, n1 = g_dinv[s1] * di;
        float4 v0 = H4[s0 * 32 + lane];
        float4 v1 = H4[s1 * 32 + lane];
        acc.x += n0 * v0.x + n1 * v1.x;
        acc.y += n0 * v0.y + n1 * v1.y;
        acc.z += n0 * v0.z + n1 * v1.z;
        acc.w += n0 * v0.w + n1 * v1.w;
    }
    if (e < e1) {
        int s0 = g_csrsrc[e];
        float n0 = g_dinv[s0] * di;
        float4 v0 = H4[s0 * 32 + lane];
        acc.x += n0 * v0.x; acc.y += n0 * v0.y;
        acc.z += n0 * v0.z; acc.w += n0 * v0.w;
    }

    float4 bb = ((const float4*)bias)[lane];
    acc.x += bb.x; acc.y += bb.y; acc.z += bb.z; acc.w += bb.w;

    float s4 = acc.x + acc.y + acc.z + acc.w;
#pragma unroll
    for (int o = 16; o; o >>= 1) s4 += __shfl_xor_sync(0xffffffffu, s4, o);
    float mu = s4 * (1.0f / 128.0f);

    float d0 = acc.x - mu, d1 = acc.y - mu, d2 = acc.z - mu, d3 = acc.w - mu;
    float q = d0 * d0 + d1 * d1 + d2 * d2 + d3 * d3;
#pragma unroll
    for (int o = 16; o; o >>= 1) q += __shfl_xor_sync(0xffffffffu, q, o);
    float inv = rsqrtf(q * (1.0f / 128.0f) + LN_EPS);

    float4 gg = ((const float4*)gam)[lane];
    float4 be = ((const float4*)bet)[lane];
    float4 o4;
    o4.x = fmaxf(d0 * inv * gg.x + be.x, 0.0f);
    o4.y = fmaxf(d1 * inv * gg.y + be.y, 0.0f);
    o4.z = fmaxf(d2 * inv * gg.z + be.z, 0.0f);
    o4.w = fmaxf(d3 * inv * gg.w + be.w, 0.0f);

    if (resid) {
        float4 rv = ((const float4*)resid)[row * 32 + lane];
        o4.x += rv.x; o4.y += rv.y; o4.z += rv.z; o4.w += rv.w;
    }
    ((float4*)out)[row * 32 + lane] = o4;
}

// ---------------- launch ----------------
extern "C" void kernel_launch(void* const* d_in, const int* in_sizes, int n_in,
                              void* d_out, int out_size) {
    const float* x   = (const float*)d_in[0];
    const int*   ei  = (const int*)d_in[1];   // int32
    const float* W1  = (const float*)d_in[2];
    const float* b1  = (const float*)d_in[3];
    const float* g1  = (const float*)d_in[4];
    const float* lb1 = (const float*)d_in[5];
    const float* W2  = (const float*)d_in[6];
    const float* b2  = (const float*)d_in[7];
    const float* g2  = (const float*)d_in[8];
    const float* lb2 = (const float*)d_in[9];
    float* out = (float*)d_out;

    cudaFuncSetAttribute(k_gemm_mma, cudaFuncAttributeMaxDynamicSharedMemorySize, GEMM_SMEM_BYTES);

    const int TB = 256;
    int gridN  = (N_NODES + TB - 1) / TB;
    int gridE4 = (N_EDGES / 4 + TB - 1) / TB;
    int gridAgg = (N_NODES * 32 + TB - 1) / TB;

    // W conversion (independent of CSR)
    k_convW<<<64, 256>>>(W1, 0);
    k_convW<<<64, 256>>>(W2, 1);

    // CSR build
    k_zero_cnt<<<gridN, TB>>>();
    k_count<<<gridE4, TB>>>(ei);
    k_scan1<<<SCAN_BLOCKS, 256>>>();
    k_scan2<<<1, 256>>>();
    k_scan3<<<SCAN_BLOCKS, 256>>>();
    k_fill<<<gridE4, TB>>>(ei);

    // layer 1
    k_gemm_mma<<<GEMM_GRID, 256, GEMM_SMEM_BYTES>>>(x, 0);
    k_agg_ln<<<gridAgg, TB>>>(b1, g1, lb1, nullptr, nullptr);

    // layer 2
    k_gemm_mma<<<GEMM_GRID, 256, GEMM_SMEM_BYTES>>>(nullptr, 1);
    k_agg_ln<<<gridAgg, TB>>>(b2, g2, lb2, x, out);
}

// round 5
// speedup vs baseline: 2.5429x; 1.0965x over previous
#include <cuda_runtime.h>
#include <cuda_bf16.h>
#include <cuda_fp16.h>
#include <cstdint>

#define N_NODES 50000
#define N_EDGES 600000
#define LN_EPS 1e-5f
#define NT 391            // ceil(50000/128) M-tiles
#define GEMM_GRID 148
#define SCAN_BLOCKS 196   // ceil(50000/256)

// smem word layout for GEMM (uint32 units); A/B rows padded to 68 words (136 bf16)
#define ROWW 68
#define SA_HI 0
#define SA_LO 8704
#define SB_HI 17408
#define SB_LO 26112
#define GEMM_SMEM_WORDS 34816
#define GEMM_SMEM_BYTES (GEMM_SMEM_WORDS * 4)

// ---------------- device scratch ----------------
__device__ __align__(16) __half g_hh[N_NODES * 128];   // GEMM output, fp16
__device__ __align__(16) float  g_tmp[N_NODES * 128];  // layer-1 activation (fp32)
__device__ float g_dinv[N_NODES];
__device__ int   g_cnt[N_NODES];
__device__ int   g_rowstart[N_NODES + 1];
__device__ int   g_cur[N_NODES];
__device__ int   g_csrsrc[N_EDGES];
__device__ int   g_part[SCAN_BLOCKS];
// bf16 W^T images (B layout: [n][k], linear): [layer][hi/lo]
__device__ __align__(16) uint4 g_wimg[2][2][2048];

// ---------------- CSR build ----------------
__global__ void k_count(const int* __restrict__ ei) {
    int b = blockIdx.x * blockDim.x + threadIdx.x;
    const int4* D = (const int4*)(ei + N_EDGES);
    int i0 = b * 2;
#pragma unroll
    for (int j = 0; j < 2; j++) {
        int i = i0 + j;
        if (i < N_EDGES / 4) {
            int4 d = D[i];
            atomicAdd(&g_cnt[d.x], 1);
            atomicAdd(&g_cnt[d.y], 1);
            atomicAdd(&g_cnt[d.z], 1);
            atomicAdd(&g_cnt[d.w], 1);
        }
    }
}

__global__ void k_scan1() {
    __shared__ int sh[256];
    int i = blockIdx.x * 256 + threadIdx.x;
    sh[threadIdx.x] = (i < N_NODES) ? g_cnt[i] : 0;
    __syncthreads();
#pragma unroll
    for (int o = 128; o; o >>= 1) {
        if (threadIdx.x < o) sh[threadIdx.x] += sh[threadIdx.x + o];
        __syncthreads();
    }
    if (threadIdx.x == 0) g_part[blockIdx.x] = sh[0];
}

// scan3 with inline cross-block prefix (scan2 folded in)
__global__ void k_scan3() {
    __shared__ int sh[256];
    __shared__ int soff;
    int t = threadIdx.x;

    // block offset = sum of g_part[0 .. blockIdx.x)
    int pre = 0;
    for (int j = t; j < blockIdx.x; j += 256) pre += g_part[j];
    sh[t] = pre;
    __syncthreads();
#pragma unroll
    for (int o = 128; o; o >>= 1) {
        if (t < o) sh[t] += sh[t + o];
        __syncthreads();
    }
    if (t == 0) soff = sh[0];
    __syncthreads();
    int off = soff;
    __syncthreads();

    // intra-block inclusive scan of counts
    int i = blockIdx.x * 256 + t;
    int c = (i < N_NODES) ? g_cnt[i] : 0;
    sh[t] = c;
    __syncthreads();
#pragma unroll
    for (int o = 1; o < 256; o <<= 1) {
        int a = (t >= o) ? sh[t - o] : 0;
        __syncthreads();
        sh[t] += a;
        __syncthreads();
    }
    if (i < N_NODES) {
        int excl = off + sh[t] - c;
        g_rowstart[i] = excl;
        g_cur[i] = excl;
        g_dinv[i] = rsqrtf((float)c + 1.0f);
    }
    if (blockIdx.x == SCAN_BLOCKS - 1 && t == 255)
        g_rowstart[N_NODES] = off + sh[255];
}

__global__ void k_fill(const int* __restrict__ ei) {
    int b = blockIdx.x * blockDim.x + threadIdx.x;
    const int4* S = (const int4*)ei;
    const int4* D = (const int4*)(ei + N_EDGES);
    int i0 = b * 2;
#pragma unroll
    for (int j = 0; j < 2; j++) {
        int i = i0 + j;
        if (i < N_EDGES / 4) {
            int4 s = S[i];
            int4 d = D[i];
            g_csrsrc[atomicAdd(&g_cur[d.x], 1)] = s.x;
            g_csrsrc[atomicAdd(&g_cur[d.y], 1)] = s.y;
            g_csrsrc[atomicAdd(&g_cur[d.z], 1)] = s.z;
            g_csrsrc[atomicAdd(&g_cur[d.w], 1)] = s.w;
        }
    }
}

// ---------------- W -> transposed bf16 hi/lo images (both layers, one kernel) ----------------
__global__ void k_convW(const float* __restrict__ W1, const float* __restrict__ W2) {
    int layer = blockIdx.y;
    const float* W = layer ? W2 : W1;
    __nv_bfloat16* hi = (__nv_bfloat16*)g_wimg[layer][0];
    __nv_bfloat16* lo = (__nv_bfloat16*)g_wimg[layer][1];
    for (int i = blockIdx.x * blockDim.x + threadIdx.x; i < 16384; i += blockDim.x * gridDim.x) {
        int n = i >> 7, k = i & 127;          // B[n][k] = W[k][n]
        float w = W[k * 128 + n];
        __nv_bfloat16 h = __float2bfloat16(w);
        __nv_bfloat16 l = __float2bfloat16(w - __bfloat162float(h));
        hi[n * 128 + k] = h;
        lo[n * 128 + k] = l;
    }
}

// ---------------- mma.sync bf16 split-precision GEMM ----------------
__device__ __forceinline__ uint32_t pack2(__nv_bfloat16 a, __nv_bfloat16 b) {
    return (uint32_t)__bfloat16_as_ushort(a) | ((uint32_t)__bfloat16_as_ushort(b) << 16);
}

__device__ __forceinline__ void mma_bf16(float* c, const uint32_t* a, const uint32_t* b) {
    asm volatile(
        "mma.sync.aligned.m16n8k16.row.col.f32.bf16.bf16.f32 "
        "{%0,%1,%2,%3}, {%4,%5,%6,%7}, {%8,%9}, {%0,%1,%2,%3};"
        : "+f"(c[0]), "+f"(c[1]), "+f"(c[2]), "+f"(c[3])
        : "r"(a[0]), "r"(a[1]), "r"(a[2]), "r"(a[3]), "r"(b[0]), "r"(b[1]));
}

// H = X @ W via D = Ah*Bh + Ah*Bl + Al*Bh; persistent CTAs over M-tiles of 128.
// Output stored fp16 into g_hh.
__global__ void __launch_bounds__(256, 1) k_gemm_mma(const float* __restrict__ Xin, int layer) {
    extern __shared__ uint32_t sw[];
    uint32_t* sAh = sw + SA_HI;
    uint32_t* sAl = sw + SA_LO;
    uint32_t* sBh = sw + SB_HI;
    uint32_t* sBl = sw + SB_LO;

    const float4* X4 = (const float4*)((layer == 0) ? Xin : g_tmp);
    int tid = threadIdx.x, wid = tid >> 5, lane = tid & 31;
    int g = lane >> 2, t = lane & 3;
    int wm = wid & 3, wn = wid >> 2;

    // stage B (W^T) hi/lo into padded smem, once
    {
        const uint4* Bh = g_wimg[layer][0];
        const uint4* Bl = g_wimg[layer][1];
#pragma unroll 4
        for (int i = tid; i < 2048; i += 256) {
            int n = i >> 4, kc = i & 15;
            *(uint4*)(sBh + n * ROWW + kc * 4) = Bh[i];
            *(uint4*)(sBl + n * ROWW + kc * 4) = Bl[i];
        }
    }
    __syncthreads();

    for (int tile = blockIdx.x; tile < NT; tile += gridDim.x) {
        int rowBase = tile * 128;

        // convert A tile fp32 -> bf16 hi/lo into padded smem
#pragma unroll 4
        for (int i = tid; i < 4096; i += 256) {      // 128 rows x 32 float4
            int r = i >> 5, c = i & 31;
            int grow = rowBase + r;
            float4 v = (grow < N_NODES) ? X4[grow * 32 + c] : make_float4(0.f, 0.f, 0.f, 0.f);
            __nv_bfloat16 h0 = __float2bfloat16(v.x), h1 = __float2bfloat16(v.y);
            __nv_bfloat16 h2 = __float2bfloat16(v.z), h3 = __float2bfloat16(v.w);
            __nv_bfloat16 l0 = __float2bfloat16(v.x - __bfloat162float(h0));
            __nv_bfloat16 l1 = __float2bfloat16(v.y - __bfloat162float(h1));
            __nv_bfloat16 l2 = __float2bfloat16(v.z - __bfloat162float(h2));
            __nv_bfloat16 l3 = __float2bfloat16(v.w - __bfloat162float(h3));
            *(uint2*)(sAh + r * ROWW + c * 2) = make_uint2(pack2(h0, h1), pack2(h2, h3));
            *(uint2*)(sAl + r * ROWW + c * 2) = make_uint2(pack2(l0, l1), pack2(l2, l3));
        }
        __syncthreads();

        float acc[2][8][4];
#pragma unroll
        for (int mi = 0; mi < 2; mi++)
#pragma unroll
            for (int ni = 0; ni < 8; ni++)
#pragma unroll
                for (int j = 0; j < 4; j++) acc[mi][ni][j] = 0.0f;

#pragma unroll
        for (int ks = 0; ks < 8; ks++) {
            int kw = ks * 8;
            uint32_t ah[2][4], al[2][4];
#pragma unroll
            for (int mi = 0; mi < 2; mi++) {
                int r0 = (wm * 32 + mi * 16 + g) * ROWW + kw + t;
                int r1 = r0 + 8 * ROWW;
                ah[mi][0] = sAh[r0]; ah[mi][1] = sAh[r1];
                ah[mi][2] = sAh[r0 + 4]; ah[mi][3] = sAh[r1 + 4];
                al[mi][0] = sAl[r0]; al[mi][1] = sAl[r1];
                al[mi][2] = sAl[r0 + 4]; al[mi][3] = sAl[r1 + 4];
            }
            uint32_t bh[8][2], bl[8][2];
#pragma unroll
            for (int ni = 0; ni < 8; ni++) {
                int nb = (wn * 64 + ni * 8 + g) * ROWW + kw + t;
                bh[ni][0] = sBh[nb]; bh[ni][1] = sBh[nb + 4];
                bl[ni][0] = sBl[nb]; bl[ni][1] = sBl[nb + 4];
            }
#pragma unroll
            for (int mi = 0; mi < 2; mi++)
#pragma unroll
                for (int ni = 0; ni < 8; ni++) {
                    mma_bf16(acc[mi][ni], ah[mi], bh[ni]);
                    mma_bf16(acc[mi][ni], ah[mi], bl[ni]);
                    mma_bf16(acc[mi][ni], al[mi], bh[ni]);
                }
        }

        // epilogue: fragments -> g_hh fp16
#pragma unroll
        for (int mi = 0; mi < 2; mi++) {
            int r0 = rowBase + wm * 32 + mi * 16 + g;
            int r1 = r0 + 8;
#pragma unroll
            for (int ni = 0; ni < 8; ni++) {
                int col = wn * 64 + ni * 8 + t * 2;
                if (r0 < N_NODES)
                    *(__half2*)&g_hh[r0 * 128 + col] =
                        __floats2half2_rn(acc[mi][ni][0], acc[mi][ni][1]);
                if (r1 < N_NODES)
                    *(__half2*)&g_hh[r1 * 128 + col] =
                        __floats2half2_rn(acc[mi][ni][2], acc[mi][ni][3]);
            }
        }
        __syncthreads();
    }
}

// ---------------- fused aggregation + bias + LayerNorm + ReLU (+ residual) ----------------
__device__ __forceinline__ float4 up4(uint2 v) {
    __half2 a = *(__half2*)&v.x;
    __half2 b = *(__half2*)&v.y;
    float2 fa = __half22float2(a);
    float2 fb = __half22float2(b);
    return make_float4(fa.x, fa.y, fb.x, fb.y);
}

__global__ void __launch_bounds__(256) k_agg_ln(const float* __restrict__ bias,
                                                const float* __restrict__ gam,
                                                const float* __restrict__ bet,
                                                const float* __restrict__ resid,
                                                float* __restrict__ outp) {
    int warp = (blockIdx.x * blockDim.x + threadIdx.x) >> 5;
    int lane = threadIdx.x & 31;
    if (warp >= N_NODES) return;
    int row = warp;

    float* out = outp ? outp : g_tmp;
    const uint2* H2 = (const uint2*)g_hh;   // 32 uint2 per row (4 halfs per lane)

    float di = g_dinv[row];
    float sl = di * di;
    float4 sv = up4(H2[row * 32 + lane]);
    float4 acc = make_float4(sv.x * sl, sv.y * sl, sv.z * sl, sv.w * sl);

    int e = g_rowstart[row];
    int e1 = g_rowstart[row + 1];
    for (; e + 4 <= e1; e += 4) {
        int s0 = g_csrsrc[e], s1 = g_csrsrc[e + 1];
        int s2 = g_csrsrc[e + 2], s3 = g_csrsrc[e + 3];
        float n0 = g_dinv[s0] * di, n1 = g_dinv[s1] * di;
        float n2 = g_dinv[s2] * di, n3 = g_dinv[s3] * di;
        uint2 r0 = H2[s0 * 32 + lane], r1 = H2[s1 * 32 + lane];
        uint2 r2 = H2[s2 * 32 + lane], r3 = H2[s3 * 32 + lane];
        float4 v0 = up4(r0), v1 = up4(r1), v2 = up4(r2), v3 = up4(r3);
        acc.x += n0 * v0.x + n1 * v1.x + n2 * v2.x + n3 * v3.x;
        acc.y += n0 * v0.y + n1 * v1.y + n2 * v2.y + n3 * v3.y;
        acc.z += n0 * v0.z + n1 * v1.z + n2 * v2.z + n3 * v3.z;
        acc.w += n0 * v0.w + n1 * v1.w + n2 * v2.w + n3 * v3.w;
    }
    for (; e < e1; e++) {
        int s0 = g_csrsrc[e];
        float n0 = g_dinv[s0] * di;
        float4 v0 = up4(H2[s0 * 32 + lane]);
        acc.x += n0 * v0.x; acc.y += n0 * v0.y;
        acc.z += n0 * v0.z; acc.w += n0 * v0.w;
    }

    float4 bb = ((const float4*)bias)[lane];
    acc.x += bb.x; acc.y += bb.y; acc.z += bb.z; acc.w += bb.w;

    float s4 = acc.x + acc.y + acc.z + acc.w;
#pragma unroll
    for (int o = 16; o; o >>= 1) s4 += __shfl_xor_sync(0xffffffffu, s4, o);
    float mu = s4 * (1.0f / 128.0f);

    float d0 = acc.x - mu, d1 = acc.y - mu, d2 = acc.z - mu, d3 = acc.w - mu;
    float q = d0 * d0 + d1 * d1 + d2 * d2 + d3 * d3;
#pragma unroll
    for (int o = 16; o; o >>= 1) q += __shfl_xor_sync(0xffffffffu, q, o);
    float inv = rsqrtf(q * (1.0f / 128.0f) + LN_EPS);

    float4 gg = ((const float4*)gam)[lane];
    float4 be = ((const float4*)bet)[lane];
    float4 o4;
    o4.x = fmaxf(d0 * inv * gg.x + be.x, 0.0f);
    o4.y = fmaxf(d1 * inv * gg.y + be.y, 0.0f);
    o4.z = fmaxf(d2 * inv * gg.z + be.z, 0.0f);
    o4.w = fmaxf(d3 * inv * gg.w + be.w, 0.0f);

    if (resid) {
        float4 rv = ((const float4*)resid)[row * 32 + lane];
        o4.x += rv.x; o4.y += rv.y; o4.z += rv.z; o4.w += rv.w;
    }
    ((float4*)out)[row * 32 + lane] = o4;
}

// ---------------- launch ----------------
extern "C" void kernel_launch(void* const* d_in, const int* in_sizes, int n_in,
                              void* d_out, int out_size) {
    const float* x   = (const float*)d_in[0];
    const int*   ei  = (const int*)d_in[1];   // int32
    const float* W1  = (const float*)d_in[2];
    const float* b1  = (const float*)d_in[3];
    const float* g1  = (const float*)d_in[4];
    const float* lb1 = (const float*)d_in[5];
    const float* W2  = (const float*)d_in[6];
    const float* b2  = (const float*)d_in[7];
    const float* g2  = (const float*)d_in[8];
    const float* lb2 = (const float*)d_in[9];
    float* out = (float*)d_out;

    cudaFuncSetAttribute(k_gemm_mma, cudaFuncAttributeMaxDynamicSharedMemorySize, GEMM_SMEM_BYTES);

    const int TB = 256;
    int gridE8 = (N_EDGES / 8 + TB - 1) / TB;    // 8 edges per thread
    int gridAgg = (N_NODES * 32 + TB - 1) / TB;

    // W conversion (both layers, one kernel)
    k_convW<<<dim3(32, 2), 256>>>(W1, W2);

    // CSR build
    void* cntPtr = nullptr;
    cudaGetSymbolAddress(&cntPtr, g_cnt);
    cudaMemsetAsync(cntPtr, 0, N_NODES * sizeof(int));
    k_count<<<gridE8, TB>>>(ei);
    k_scan1<<<SCAN_BLOCKS, 256>>>();
    k_scan3<<<SCAN_BLOCKS, 256>>>();
    k_fill<<<gridE8, TB>>>(ei);

    // layer 1
    k_gemm_mma<<<GEMM_GRID, 256, GEMM_SMEM_BYTES>>>(x, 0);
    k_agg_ln<<<gridAgg, TB>>>(b1, g1, lb1, nullptr, nullptr);

    // layer 2
    k_gemm_mma<<<GEMM_GRID, 256, GEMM_SMEM_BYTES>>>(nullptr, 1);
    k_agg_ln<<<gridAgg, TB>>>(b2, g2, lb2, x, out);
}

// round 8
// speedup vs baseline: 2.8960x; 1.1388x over previous
#include <cuda_runtime.h>
#include <cuda_bf16.h>
#include <cuda_fp16.h>
#include <cstdint>

#define N_NODES 50000
#define N_EDGES 600000
#define LN_EPS 1e-5f
#define NT 391            // ceil(50000/128) M-tiles
#define NROWS_PAD (NT * 128)   // 50048
#define GEMM_GRID 148
#define SCAN_BLOCKS 196   // ceil(50000/256)

// smem word layout for GEMM (uint32 units); A/B rows padded to 68 words (136 bf16)
#define ROWW 68
#define SA_HI 0
#define SA_LO 8704
#define SB_HI 17408
#define SB_LO 26112
#define GEMM_SMEM_WORDS 34816
#define GEMM_SMEM_BYTES (GEMM_SMEM_WORDS * 4)

// ---------------- device scratch ----------------
__device__ __align__(16) __half g_hh[N_NODES * 128];        // GEMM output, fp16
__device__ __align__(16) uint32_t g_ah[NROWS_PAD * 64];     // layer-1 act, bf16 hi (64 u32/row)
__device__ __align__(16) uint32_t g_al[NROWS_PAD * 64];     // layer-1 act, bf16 lo
__device__ float g_dinv[N_NODES];
__device__ int   g_cnt[N_NODES];
__device__ int   g_rowstart[N_NODES + 1];
__device__ int   g_cur[N_NODES];
__device__ int   g_csrsrc[N_EDGES];
__device__ int   g_part[SCAN_BLOCKS];
// bf16 W^T images (B layout: [n][k], linear): [layer][hi/lo]
__device__ __align__(16) uint4 g_wimg[2][2][2048];

// ---------------- CSR build ----------------
__global__ void k_count(const int* __restrict__ ei) {
    int i = blockIdx.x * blockDim.x + threadIdx.x;
    if (i < N_EDGES / 4) {
        int4 d = ((const int4*)(ei + N_EDGES))[i];
        atomicAdd(&g_cnt[d.x], 1);
        atomicAdd(&g_cnt[d.y], 1);
        atomicAdd(&g_cnt[d.z], 1);
        atomicAdd(&g_cnt[d.w], 1);
    }
}

__global__ void k_scan1() {
    __shared__ int sh[256];
    int i = blockIdx.x * 256 + threadIdx.x;
    sh[threadIdx.x] = (i < N_NODES) ? g_cnt[i] : 0;
    __syncthreads();
#pragma unroll
    for (int o = 128; o; o >>= 1) {
        if (threadIdx.x < o) sh[threadIdx.x] += sh[threadIdx.x + o];
        __syncthreads();
    }
    if (threadIdx.x == 0) g_part[blockIdx.x] = sh[0];
}

// prefix + per-node CSR init, shuffle-based (2 barriers)
__global__ void k_scan3() {
    __shared__ int wsum[8];
    int t = threadIdx.x, lane = t & 31, w = t >> 5;

    // cross-block offset = sum g_part[0 .. bid)
    int pre = 0;
    for (int j = t; j < blockIdx.x; j += 256) pre += g_part[j];
#pragma unroll
    for (int o = 16; o; o >>= 1) pre += __shfl_xor_sync(0xffffffffu, pre, o);
    if (lane == 0) wsum[w] = pre;
    __syncthreads();
    int blockoff = 0;
#pragma unroll
    for (int j = 0; j < 8; j++) blockoff += wsum[j];
    __syncthreads();

    // intra-block inclusive scan (warp shuffle + warp offsets)
    int i = blockIdx.x * 256 + t;
    int c = (i < N_NODES) ? g_cnt[i] : 0;
    int v = c;
#pragma unroll
    for (int o = 1; o < 32; o <<= 1) {
        int n = __shfl_up_sync(0xffffffffu, v, o);
        if (lane >= o) v += n;
    }
    if (lane == 31) wsum[w] = v;
    __syncthreads();
    int woff = 0;
#pragma unroll
    for (int j = 0; j < 8; j++)
        if (j < w) woff += wsum[j];

    if (i < N_NODES) {
        int excl = blockoff + woff + v - c;
        g_rowstart[i] = excl;
        g_cur[i] = excl;
        g_dinv[i] = rsqrtf((float)c + 1.0f);
    }
    if (blockIdx.x == SCAN_BLOCKS - 1 && t == 255)
        g_rowstart[N_NODES] = blockoff + woff + v;
}

__global__ void k_fill(const int* __restrict__ ei) {
    int i = blockIdx.x * blockDim.x + threadIdx.x;
    if (i < N_EDGES / 4) {
        int4 s = ((const int4*)ei)[i];
        int4 d = ((const int4*)(ei + N_EDGES))[i];
        g_csrsrc[atomicAdd(&g_cur[d.x], 1)] = s.x;
        g_csrsrc[atomicAdd(&g_cur[d.y], 1)] = s.y;
        g_csrsrc[atomicAdd(&g_cur[d.z], 1)] = s.z;
        g_csrsrc[atomicAdd(&g_cur[d.w], 1)] = s.w;
    }
}

// ---------------- W -> transposed bf16 hi/lo images (both layers) ----------------
__global__ void k_convW(const float* __restrict__ W1, const float* __restrict__ W2) {
    int layer = blockIdx.y;
    const float* W = layer ? W2 : W1;
    __nv_bfloat16* hi = (__nv_bfloat16*)g_wimg[layer][0];
    __nv_bfloat16* lo = (__nv_bfloat16*)g_wimg[layer][1];
    for (int i = blockIdx.x * blockDim.x + threadIdx.x; i < 16384; i += blockDim.x * gridDim.x) {
        int n = i >> 7, k = i & 127;          // B[n][k] = W[k][n]
        float w = W[k * 128 + n];
        __nv_bfloat16 h = __float2bfloat16(w);
        __nv_bfloat16 l = __float2bfloat16(w - __bfloat162float(h));
        hi[n * 128 + k] = h;
        lo[n * 128 + k] = l;
    }
}

// ---------------- mma.sync bf16 split-precision GEMM ----------------
__device__ __forceinline__ uint32_t pack2(__nv_bfloat16 a, __nv_bfloat16 b) {
    return (uint32_t)__bfloat16_as_ushort(a) | ((uint32_t)__bfloat16_as_ushort(b) << 16);
}

__device__ __forceinline__ void mma_bf16(float* c, const uint32_t* a, const uint32_t* b) {
    asm volatile(
        "mma.sync.aligned.m16n8k16.row.col.f32.bf16.bf16.f32 "
        "{%0,%1,%2,%3}, {%4,%5,%6,%7}, {%8,%9}, {%0,%1,%2,%3};"
        : "+f"(c[0]), "+f"(c[1]), "+f"(c[2]), "+f"(c[3])
        : "r"(a[0]), "r"(a[1]), "r"(a[2]), "r"(a[3]), "r"(b[0]), "r"(b[1]));
}

// H = X @ W via D = Ah*Bh + Ah*Bl + Al*Bh; persistent CTAs over M-tiles of 128.
// layer 0: A from fp32 Xin (convert). layer 1: A from pre-split g_ah/g_al (copy).
__global__ void __launch_bounds__(256, 1) k_gemm_mma(const float* __restrict__ Xin, int layer) {
    extern __shared__ uint32_t sw[];
    uint32_t* sAh = sw + SA_HI;
    uint32_t* sAl = sw + SA_LO;
    uint32_t* sBh = sw + SB_HI;
    uint32_t* sBl = sw + SB_LO;

    const float4* X4 = (const float4*)Xin;
    int tid = threadIdx.x, wid = tid >> 5, lane = tid & 31;
    int g = lane >> 2, t = lane & 3;
    int wm = wid & 3, wn = wid >> 2;

    // stage B (W^T) hi/lo into padded smem, once
    {
        const uint4* Bh = g_wimg[layer][0];
        const uint4* Bl = g_wimg[layer][1];
#pragma unroll 4
        for (int i = tid; i < 2048; i += 256) {
            int n = i >> 4, kc = i & 15;
            *(uint4*)(sBh + n * ROWW + kc * 4) = Bh[i];
            *(uint4*)(sBl + n * ROWW + kc * 4) = Bl[i];
        }
    }
    __syncthreads();

    for (int tile = blockIdx.x; tile < NT; tile += gridDim.x) {
        int rowBase = tile * 128;

        if (layer == 0) {
            // convert A tile fp32 -> bf16 hi/lo into padded smem
#pragma unroll 4
            for (int i = tid; i < 4096; i += 256) {      // 128 rows x 32 float4
                int r = i >> 5, c = i & 31;
                int grow = rowBase + r;
                float4 v = (grow < N_NODES) ? X4[grow * 32 + c] : make_float4(0.f, 0.f, 0.f, 0.f);
                __nv_bfloat16 h0 = __float2bfloat16(v.x), h1 = __float2bfloat16(v.y);
                __nv_bfloat16 h2 = __float2bfloat16(v.z), h3 = __float2bfloat16(v.w);
                __nv_bfloat16 l0 = __float2bfloat16(v.x - __bfloat162float(h0));
                __nv_bfloat16 l1 = __float2bfloat16(v.y - __bfloat162float(h1));
                __nv_bfloat16 l2 = __float2bfloat16(v.z - __bfloat162float(h2));
                __nv_bfloat16 l3 = __float2bfloat16(v.w - __bfloat162float(h3));
                *(uint2*)(sAh + r * ROWW + c * 2) = make_uint2(pack2(h0, h1), pack2(h2, h3));
                *(uint2*)(sAl + r * ROWW + c * 2) = make_uint2(pack2(l0, l1), pack2(l2, l3));
            }
        } else {
            // copy pre-split A tile (bf16 hi/lo) into padded smem: 128 rows x 16 uint4
#pragma unroll 4
            for (int i = tid; i < 2048; i += 256) {
                int r = i >> 4, q = i & 15;
                int gi = (rowBase + r) * 16 + q;         // uint4 index (row stride 16)
                *(uint4*)(sAh + r * ROWW + q * 4) = ((const uint4*)g_ah)[gi];
                *(uint4*)(sAl + r * ROWW + q * 4) = ((const uint4*)g_al)[gi];
            }
        }
        __syncthreads();

        float acc[2][8][4];
#pragma unroll
        for (int mi = 0; mi < 2; mi++)
#pragma unroll
            for (int ni = 0; ni < 8; ni++)
#pragma unroll
                for (int j = 0; j < 4; j++) acc[mi][ni][j] = 0.0f;

#pragma unroll
        for (int ks = 0; ks < 8; ks++) {
            int kw = ks * 8;
            uint32_t ah[2][4], al[2][4];
#pragma unroll
            for (int mi = 0; mi < 2; mi++) {
                int r0 = (wm * 32 + mi * 16 + g) * ROWW + kw + t;
                int r1 = r0 + 8 * ROWW;
                ah[mi][0] = sAh[r0]; ah[mi][1] = sAh[r1];
                ah[mi][2] = sAh[r0 + 4]; ah[mi][3] = sAh[r1 + 4];
                al[mi][0] = sAl[r0]; al[mi][1] = sAl[r1];
                al[mi][2] = sAl[r0 + 4]; al[mi][3] = sAl[r1 + 4];
            }
            uint32_t bh[8][2], bl[8][2];
#pragma unroll
            for (int ni = 0; ni < 8; ni++) {
                int nb = (wn * 64 + ni * 8 + g) * ROWW + kw + t;
                bh[ni][0] = sBh[nb]; bh[ni][1] = sBh[nb + 4];
                bl[ni][0] = sBl[nb]; bl[ni][1] = sBl[nb + 4];
            }
#pragma unroll
            for (int mi = 0; mi < 2; mi++)
#pragma unroll
                for (int ni = 0; ni < 8; ni++) {
                    mma_bf16(acc[mi][ni], ah[mi], bh[ni]);
                    mma_bf16(acc[mi][ni], ah[mi], bl[ni]);
                    mma_bf16(acc[mi][ni], al[mi], bh[ni]);
                }
        }

        // epilogue: fragments -> g_hh fp16
#pragma unroll
        for (int mi = 0; mi < 2; mi++) {
            int r0 = rowBase + wm * 32 + mi * 16 + g;
            int r1 = r0 + 8;
#pragma unroll
            for (int ni = 0; ni < 8; ni++) {
                int col = wn * 64 + ni * 8 + t * 2;
                if (r0 < N_NODES)
                    *(__half2*)&g_hh[r0 * 128 + col] =
                        __floats2half2_rn(acc[mi][ni][0], acc[mi][ni][1]);
                if (r1 < N_NODES)
                    *(__half2*)&g_hh[r1 * 128 + col] =
                        __floats2half2_rn(acc[mi][ni][2], acc[mi][ni][3]);
            }
        }
        __syncthreads();
    }
}

// ---------------- fused aggregation + bias + LayerNorm + ReLU (+ residual) ----------------
__device__ __forceinline__ float4 up4(uint2 v) {
    __half2 a = *(__half2*)&v.x;
    __half2 b = *(__half2*)&v.y;
    float2 fa = __half22float2(a);
    float2 fb = __half22float2(b);
    return make_float4(fa.x, fa.y, fb.x, fb.y);
}

// outp == nullptr: write bf16 hi/lo split images (g_ah/g_al) for the next GEMM.
// outp != nullptr: add resid, write fp32 to outp.
__global__ void __launch_bounds__(256) k_agg_ln(const float* __restrict__ bias,
                                                const float* __restrict__ gam,
                                                const float* __restrict__ bet,
                                                const float* __restrict__ resid,
                                                float* __restrict__ outp) {
    int warp = (blockIdx.x * blockDim.x + threadIdx.x) >> 5;
    int lane = threadIdx.x & 31;
    if (warp >= N_NODES) return;
    int row = warp;

    const uint2* H2 = (const uint2*)g_hh;   // 32 uint2 per row (4 halfs per lane)

    float di = g_dinv[row];
    float sl = di * di;
    float4 sv = up4(H2[row * 32 + lane]);
    float4 acc = make_float4(sv.x * sl, sv.y * sl, sv.z * sl, sv.w * sl);

    int e = g_rowstart[row];
    int e1 = g_rowstart[row + 1];
    for (; e + 4 <= e1; e += 4) {
        int s0 = g_csrsrc[e], s1 = g_csrsrc[e + 1];
        int s2 = g_csrsrc[e + 2], s3 = g_csrsrc[e + 3];
        float n0 = g_dinv[s0] * di, n1 = g_dinv[s1] * di;
        float n2 = g_dinv[s2] * di, n3 = g_dinv[s3] * di;
        uint2 r0 = H2[s0 * 32 + lane], r1 = H2[s1 * 32 + lane];
        uint2 r2 = H2[s2 * 32 + lane], r3 = H2[s3 * 32 + lane];
        float4 v0 = up4(r0), v1 = up4(r1), v2 = up4(r2), v3 = up4(r3);
        acc.x += n0 * v0.x + n1 * v1.x + n2 * v2.x + n3 * v3.x;
        acc.y += n0 * v0.y + n1 * v1.y + n2 * v2.y + n3 * v3.y;
        acc.z += n0 * v0.z + n1 * v1.z + n2 * v2.z + n3 * v3.z;
        acc.w += n0 * v0.w + n1 * v1.w + n2 * v2.w + n3 * v3.w;
    }
    for (; e < e1; e++) {
        int s0 = g_csrsrc[e];
        float n0 = g_dinv[s0] * di;
        float4 v0 = up4(H2[s0 * 32 + lane]);
        acc.x += n0 * v0.x; acc.y += n0 * v0.y;
        acc.z += n0 * v0.z; acc.w += n0 * v0.w;
    }

    float4 bb = ((const float4*)bias)[lane];
    acc.x += bb.x; acc.y += bb.y; acc.z += bb.z; acc.w += bb.w;

    float s4 = acc.x + acc.y + acc.z + acc.w;
#pragma unroll
    for (int o = 16; o; o >>= 1) s4 += __shfl_xor_sync(0xffffffffu, s4, o);
    float mu = s4 * (1.0f / 128.0f);

    float d0 = acc.x - mu, d1 = acc.y - mu, d2 = acc.z - mu, d3 = acc.w - mu;
    float q = d0 * d0 + d1 * d1 + d2 * d2 + d3 * d3;
#pragma unroll
    for (int o = 16; o; o >>= 1) q += __shfl_xor_sync(0xffffffffu, q, o);
    float inv = rsqrtf(q * (1.0f / 128.0f) + LN_EPS);

    float4 gg = ((const float4*)gam)[lane];
    float4 be = ((const float4*)bet)[lane];
    float4 o4;
    o4.x = fmaxf(d0 * inv * gg.x + be.x, 0.0f);
    o4.y = fmaxf(d1 * inv * gg.y + be.y, 0.0f);
    o4.z = fmaxf(d2 * inv * gg.z + be.z, 0.0f);
    o4.w = fmaxf(d3 * inv * gg.w + be.w, 0.0f);

    if (outp) {
        float4 rv = ((const float4*)resid)[row * 32 + lane];
        o4.x += rv.x; o4.y += rv.y; o4.z += rv.z; o4.w += rv.w;
        ((float4*)outp)[row * 32 + lane] = o4;
    } else {
        // split to bf16 hi/lo for next GEMM (row stride 64 uint32)
        __nv_bfloat16 h0 = __float2bfloat16(o4.x), h1 = __float2bfloat16(o4.y);
        __nv_bfloat16 h2 = __float2bfloat16(o4.z), h3 = __float2bfloat16(o4.w);
        __nv_bfloat16 l0 = __float2bfloat16(o4.x - __bfloat162float(h0));
        __nv_bfloat16 l1 = __float2bfloat16(o4.y - __bfloat162float(h1));
        __nv_bfloat16 l2 = __float2bfloat16(o4.z - __bfloat162float(h2));
        __nv_bfloat16 l3 = __float2bfloat16(o4.w - __bfloat162float(h3));
        int idx = row * 64 + lane * 2;
        *(uint2*)&g_ah[idx] = make_uint2(pack2(h0, h1), pack2(h2, h3));
        *(uint2*)&g_al[idx] = make_uint2(pack2(l0, l1), pack2(l2, l3));
    }
}

// zero-pad the tail rows of the split images once per launch (rows 50000..50047)
__global__ void k_padtail() {
    int i = blockIdx.x * blockDim.x + threadIdx.x;
    int base = N_NODES * 64;
    int total = (NROWS_PAD - N_NODES) * 64;
    if (i < total) { g_ah[base + i] = 0; g_al[base + i] = 0; }
}

// ---------------- launch ----------------
extern "C" void kernel_launch(void* const* d_in, const int* in_sizes, int n_in,
                              void* d_out, int out_size) {
    const float* x   = (const float*)d_in[0];
    const int*   ei  = (const int*)d_in[1];   // int32
    const float* W1  = (const float*)d_in[2];
    const float* b1  = (const float*)d_in[3];
    const float* g1  = (const float*)d_in[4];
    const float* lb1 = (const float*)d_in[5];
    const float* W2  = (const float*)d_in[6];
    const float* b2  = (const float*)d_in[7];
    const float* g2  = (const float*)d_in[8];
    const float* lb2 = (const float*)d_in[9];
    float* out = (float*)d_out;

    static bool inited = false;
    static cudaStream_t s1;
    static cudaEvent_t evFork, evJoin;
    if (!inited) {
        cudaStreamCreate(&s1);
        cudaEventCreateWithFlags(&evFork, cudaEventDisableTiming);
        cudaEventCreateWithFlags(&evJoin, cudaEventDisableTiming);
        cudaFuncSetAttribute(k_gemm_mma, cudaFuncAttributeMaxDynamicSharedMemorySize,
                             GEMM_SMEM_BYTES);
        inited = true;
    }

    const int TB = 256;
    int gridE4 = (N_EDGES / 4 + TB - 1) / TB;
    int gridAgg = (N_NODES * 32 + TB - 1) / TB;

    // fork: branch A (s1) = convW + pad + gemm1; branch B (stream 0) = CSR build
    cudaEventRecord(evFork, 0);
    cudaStreamWaitEvent(s1, evFork, 0);

    k_convW<<<dim3(32, 2), 256, 0, s1>>>(W1, W2);
    k_padtail<<<12, 256, 0, s1>>>();
    k_gemm_mma<<<GEMM_GRID, 256, GEMM_SMEM_BYTES, s1>>>(x, 0);
    cudaEventRecord(evJoin, s1);

    void* cntPtr = nullptr;
    cudaGetSymbolAddress(&cntPtr, g_cnt);
    cudaMemsetAsync(cntPtr, 0, N_NODES * sizeof(int));
    k_count<<<gridE4, TB>>>(ei);
    k_scan1<<<SCAN_BLOCKS, 256>>>();
    k_scan3<<<SCAN_BLOCKS, 256>>>();
    k_fill<<<gridE4, TB>>>(ei);

    // join
    cudaStreamWaitEvent(0, evJoin, 0);

    // layer 1 epilogue -> split images; layer 2
    k_agg_ln<<<gridAgg, TB>>>(b1, g1, lb1, nullptr, nullptr);
    k_gemm_mma<<<GEMM_GRID, 256, GEMM_SMEM_BYTES>>>(nullptr, 1);
    k_agg_ln<<<gridAgg, TB>>>(b2, g2, lb2, x, out);
}